// round 6
// baseline (speedup 1.0000x reference)
#include <cuda_runtime.h>
#include <cuda_fp16.h>
#include <cstdint>
#include <cstddef>

#define BB 2
#define SS 2048
#define HH 16
#define DD 64
#define DE 1024
#define NT (SS / 64)

// Projected Q/K/V in fp16, layout [b*H + h][s][d]. Q pre-scaled by log2e/8.
__device__ __half g_Q[BB*HH*SS*DD];
__device__ __half g_K[BB*HH*SS*DD];
__device__ __half g_V[BB*HH*SS*DD];

#define KSTR 72                      // smem row stride in halves
#define TILE_BYTES (64 * KSTR * 2)   // 9216 B per K or V buffer

__device__ __forceinline__ void mma16816(float* d, const uint32_t* a,
                                         uint32_t b0, uint32_t b1) {
    asm volatile(
        "mma.sync.aligned.m16n8k16.row.col.f32.f16.f16.f32 "
        "{%0,%1,%2,%3}, {%4,%5,%6,%7}, {%8,%9}, {%0,%1,%2,%3};\n"
        : "+f"(d[0]), "+f"(d[1]), "+f"(d[2]), "+f"(d[3])
        : "r"(a[0]), "r"(a[1]), "r"(a[2]), "r"(a[3]), "r"(b0), "r"(b1));
}

__device__ __forceinline__ void ldsm_x4(uint32_t& r0, uint32_t& r1,
                                        uint32_t& r2, uint32_t& r3, uint32_t a) {
    asm volatile("ldmatrix.sync.aligned.m8n8.x4.shared.b16 {%0,%1,%2,%3}, [%4];\n"
                 : "=r"(r0), "=r"(r1), "=r"(r2), "=r"(r3) : "r"(a));
}

__device__ __forceinline__ void ldsm_x4_t(uint32_t& r0, uint32_t& r1,
                                          uint32_t& r2, uint32_t& r3, uint32_t a) {
    asm volatile("ldmatrix.sync.aligned.m8n8.x4.trans.shared.b16 {%0,%1,%2,%3}, [%4];\n"
                 : "=r"(r0), "=r"(r1), "=r"(r2), "=r"(r3) : "r"(a));
}

__device__ __forceinline__ uint32_t smem_u32(const void* p) {
    return (uint32_t)__cvta_generic_to_shared(p);
}

__device__ __forceinline__ void cp16(uint32_t dst, const void* src) {
    asm volatile("cp.async.ca.shared.global [%0], [%1], 16;\n"
                 :: "r"(dst), "l"(src));
}

__device__ __forceinline__ uint32_t pack2(__half x, __half y) {
    __half2 t = __halves2half2(x, y);
    return *reinterpret_cast<uint32_t*>(&t);
}

// ---------------------------------------------------------------------------
// Projection via hi/lo-split fp16 HMMA (effectively fp32-accurate).
// grid (S/64, H, 3*B), 128 threads = 4 warps; warp w computes 16 s-rows.
// ---------------------------------------------------------------------------
__global__ __launch_bounds__(128) void proj_kernel(const float* __restrict__ xq,
                                                   const float* __restrict__ xk,
                                                   const float* __restrict__ xv,
                                                   const float* __restrict__ Wq,
                                                   const float* __restrict__ Wk,
                                                   const float* __restrict__ Wv) {
    __shared__ __align__(16) __half Xh[64 * KSTR];
    __shared__ __align__(16) __half Xl[64 * KSTR];
    __shared__ __align__(16) __half Wh[64 * KSTR];
    __shared__ __align__(16) __half Wl[64 * KSTR];

    int which = blockIdx.z / BB;          // 0=Q 1=K 2=V
    int b = blockIdx.z % BB;
    int h = blockIdx.y, s0 = blockIdx.x * 64;
    int t = threadIdx.x, w = t >> 5, lane = t & 31;
    int g = lane >> 2, qr = lane & 3;

    const float* x = (which == 0) ? xq : (which == 1) ? xk : xv;
    const float* W = (which == 0) ? Wq : (which == 1) ? Wk : Wv;
    __half* y      = (which == 0) ? g_Q : (which == 1) ? g_K : g_V;
    // Q gets 1/sqrt(64) * log2(e) folded in (softmax runs in exp2 domain)
    float sc = (which == 0) ? 0.125f * 1.44269504088896f : 1.0f;

    const float* xb = x + ((size_t)(b * SS + s0)) * DE + h * DD;
    for (int i = t; i < 4096; i += 128) {
        int r = i >> 6, d = i & 63;
        float xv_ = xb[(size_t)r * DE + d];
        __half hi = __float2half_rn(xv_);
        Xh[r * KSTR + d] = hi;
        Xl[r * KSTR + d] = __float2half_rn(xv_ - __half2float(hi));
        float wv_ = W[i];
        __half whi = __float2half_rn(wv_);
        Wh[r * KSTR + d] = whi;
        Wl[r * KSTR + d] = __float2half_rn(wv_ - __half2float(whi));
    }
    __syncthreads();

    uint32_t aH[4][4], aL[4][4];
    const __half* Xh0 = Xh + (w * 16) * KSTR;
    const __half* Xl0 = Xl + (w * 16) * KSTR;
#pragma unroll
    for (int kk = 0; kk < 4; kk++) {
        int c = kk * 16 + qr * 2;
        aH[kk][0] = *(const uint32_t*)(Xh0 + g * KSTR + c);
        aH[kk][1] = *(const uint32_t*)(Xh0 + (g + 8) * KSTR + c);
        aH[kk][2] = *(const uint32_t*)(Xh0 + g * KSTR + c + 8);
        aH[kk][3] = *(const uint32_t*)(Xh0 + (g + 8) * KSTR + c + 8);
        aL[kk][0] = *(const uint32_t*)(Xl0 + g * KSTR + c);
        aL[kk][1] = *(const uint32_t*)(Xl0 + (g + 8) * KSTR + c);
        aL[kk][2] = *(const uint32_t*)(Xl0 + g * KSTR + c + 8);
        aL[kk][3] = *(const uint32_t*)(Xl0 + (g + 8) * KSTR + c + 8);
    }

    float acc[8][4];
#pragma unroll
    for (int n = 0; n < 8; n++)
#pragma unroll
        for (int j = 0; j < 4; j++) acc[n][j] = 0.f;

    uint32_t whAddr = smem_u32(Wh) + ((lane & 7) * KSTR + (lane >> 3) * 8) * 2;
    uint32_t wlAddr = smem_u32(Wl) + ((lane & 7) * KSTR + (lane >> 3) * 8) * 2;
#pragma unroll
    for (int n = 0; n < 8; n++) {
#pragma unroll
        for (int kp = 0; kp < 2; kp++) {
            uint32_t off = (n * 8 * KSTR + kp * 32) * 2;
            uint32_t h00, h01, h10, h11, l00, l01, l10, l11;
            ldsm_x4(h00, h01, h10, h11, whAddr + off);
            ldsm_x4(l00, l01, l10, l11, wlAddr + off);
            mma16816(acc[n], aH[kp * 2], h00, h01);
            mma16816(acc[n], aL[kp * 2], h00, h01);
            mma16816(acc[n], aH[kp * 2], l00, l01);
            mma16816(acc[n], aH[kp * 2 + 1], h10, h11);
            mma16816(acc[n], aL[kp * 2 + 1], h10, h11);
            mma16816(acc[n], aH[kp * 2 + 1], l10, l11);
        }
    }

    __half* yb = y + ((size_t)(b * HH + h) * SS + s0) * DD;
    int r0 = w * 16 + g, r1 = r0 + 8;
#pragma unroll
    for (int n = 0; n < 8; n++) {
        int col = n * 8 + qr * 2;
        *(uint32_t*)(yb + (size_t)r0 * DD + col) =
            pack2(__float2half_rn(acc[n][0] * sc), __float2half_rn(acc[n][1] * sc));
        *(uint32_t*)(yb + (size_t)r1 * DD + col) =
            pack2(__float2half_rn(acc[n][2] * sc), __float2half_rn(acc[n][3] * sc));
    }
}

// ---------------------------------------------------------------------------
// Tensor-core flash attention, cp.async double-buffered K/V, exp2 softmax.
// grid (S/64, H, B), 128 threads = 4 warps, forced 4 CTAs/SM.
// ---------------------------------------------------------------------------
__global__ __launch_bounds__(128, 4) void attn_kernel(float* __restrict__ out) {
    __shared__ __align__(16) __half Ks[2][64 * KSTR];
    __shared__ __align__(16) __half Vs[2][64 * KSTR];

    int b = blockIdx.z, h = blockIdx.y, s0 = blockIdx.x * 64;
    int t = threadIdx.x, w = t >> 5, lane = t & 31;
    int g = lane >> 2, qr = lane & 3;
    size_t bh = (size_t)(b * HH + h);
    const __half* Qg = g_Q + bh * SS * DD + (size_t)(s0 + w * 16) * DD;
    const __half* Kg = g_K + bh * SS * DD;
    const __half* Vg = g_V + bh * SS * DD;

    // per-thread cp.async targets: 4 contiguous 16B chunks (=64B) per tensor
    int c0 = t * 4;                                  // chunk index, 8 chunks/row
    uint32_t ksDst = smem_u32(&Ks[0][(c0 >> 3) * KSTR + (c0 & 7) * 8]);
    uint32_t vsDst = smem_u32(&Vs[0][(c0 >> 3) * KSTR + (c0 & 7) * 8]);

    // Q A-fragments (16 regs), persistent.
    uint32_t aQ[4][4];
#pragma unroll
    for (int kk = 0; kk < 4; kk++) {
        int c = kk * 16 + qr * 2;
        aQ[kk][0] = *(const uint32_t*)(Qg + (size_t)g * DD + c);
        aQ[kk][1] = *(const uint32_t*)(Qg + (size_t)(g + 8) * DD + c);
        aQ[kk][2] = *(const uint32_t*)(Qg + (size_t)g * DD + c + 8);
        aQ[kk][3] = *(const uint32_t*)(Qg + (size_t)(g + 8) * DD + c + 8);
    }

    float o[8][4];
#pragma unroll
    for (int dn = 0; dn < 8; dn++)
#pragma unroll
        for (int j = 0; j < 4; j++) o[dn][j] = 0.f;
    float m0 = -1e30f, m1 = -1e30f, l0 = 0.f, l1 = 0.f;

    uint32_t kAddr = smem_u32(Ks) + ((lane & 7) * KSTR + (lane >> 3) * 8) * 2;
    uint32_t vAddr = smem_u32(Vs) + (lane * KSTR) * 2;

    // prologue: stage tile 0 into buffer 0
    {
        const __half* K0 = Kg;
        const __half* V0 = Vg;
#pragma unroll
        for (int j = 0; j < 4; j++) {
            cp16(ksDst + j * 16, K0 + (size_t)(c0 + j) * 8);
            cp16(vsDst + j * 16, V0 + (size_t)(c0 + j) * 8);
        }
        asm volatile("cp.async.commit_group;\n");
    }

    for (int kt = 0; kt < NT; kt++) {
        int cur = kt & 1;
        if (kt + 1 < NT) {
            const __half* K1 = Kg + (size_t)(kt + 1) * 64 * DD;
            const __half* V1 = Vg + (size_t)(kt + 1) * 64 * DD;
            uint32_t kd = ksDst + (cur ^ 1) * TILE_BYTES;
            uint32_t vd = vsDst + (cur ^ 1) * TILE_BYTES;
#pragma unroll
            for (int j = 0; j < 4; j++) {
                cp16(kd + j * 16, K1 + (size_t)(c0 + j) * 8);
                cp16(vd + j * 16, V1 + (size_t)(c0 + j) * 8);
            }
            asm volatile("cp.async.commit_group;\n");
            asm volatile("cp.async.wait_group 1;\n");
        } else {
            asm volatile("cp.async.wait_group 0;\n");
        }
        __syncthreads();

        uint32_t kA = kAddr + cur * TILE_BYTES;
        uint32_t vA = vAddr + cur * TILE_BYTES;

        // S = Q K^T (scores already in log2 domain via Q pre-scale)
        float s[8][4];
#pragma unroll
        for (int n = 0; n < 8; n++) {
#pragma unroll
            for (int j = 0; j < 4; j++) s[n][j] = 0.f;
#pragma unroll
            for (int kp = 0; kp < 2; kp++) {
                uint32_t b00, b01, b10, b11;
                ldsm_x4(b00, b01, b10, b11, kA + (n * 8 * KSTR + kp * 32) * 2);
                mma16816(s[n], aQ[kp * 2], b00, b01);
                mma16816(s[n], aQ[kp * 2 + 1], b10, b11);
            }
        }

        // streaming softmax in exp2 domain
        float rx0 = -1e30f, rx1 = -1e30f;
#pragma unroll
        for (int n = 0; n < 8; n++) {
            rx0 = fmaxf(rx0, fmaxf(s[n][0], s[n][1]));
            rx1 = fmaxf(rx1, fmaxf(s[n][2], s[n][3]));
        }
        rx0 = fmaxf(rx0, __shfl_xor_sync(0xffffffffu, rx0, 1));
        rx0 = fmaxf(rx0, __shfl_xor_sync(0xffffffffu, rx0, 2));
        rx1 = fmaxf(rx1, __shfl_xor_sync(0xffffffffu, rx1, 1));
        rx1 = fmaxf(rx1, __shfl_xor_sync(0xffffffffu, rx1, 2));
        float mn0 = fmaxf(m0, rx0), mn1 = fmaxf(m1, rx1);
        float cf0 = exp2f(m0 - mn0), cf1 = exp2f(m1 - mn1);
        m0 = mn0; m1 = mn1;

        float sum0 = 0.f, sum1 = 0.f;
        uint32_t aP[4][4];
#pragma unroll
        for (int n = 0; n < 8; n++) {
            float e0 = exp2f(s[n][0] - mn0);
            float e1 = exp2f(s[n][1] - mn0);
            float e2 = exp2f(s[n][2] - mn1);
            float e3 = exp2f(s[n][3] - mn1);
            sum0 += e0 + e1; sum1 += e2 + e3;
            aP[n >> 1][(n & 1) * 2 + 0] = pack2(__float2half_rn(e0), __float2half_rn(e1));
            aP[n >> 1][(n & 1) * 2 + 1] = pack2(__float2half_rn(e2), __float2half_rn(e3));
        }
        sum0 += __shfl_xor_sync(0xffffffffu, sum0, 1);
        sum0 += __shfl_xor_sync(0xffffffffu, sum0, 2);
        sum1 += __shfl_xor_sync(0xffffffffu, sum1, 1);
        sum1 += __shfl_xor_sync(0xffffffffu, sum1, 2);
        l0 = l0 * cf0 + sum0;
        l1 = l1 * cf1 + sum1;

#pragma unroll
        for (int dn = 0; dn < 8; dn++) {
            o[dn][0] *= cf0; o[dn][1] *= cf0;
            o[dn][2] *= cf1; o[dn][3] *= cf1;
        }

        // O += P @ V
#pragma unroll
        for (int dn = 0; dn < 8; dn++) {
#pragma unroll
            for (int kp = 0; kp < 2; kp++) {
                uint32_t v00, v01, v10, v11;
                ldsm_x4_t(v00, v01, v10, v11,
                          vA + (kp * 32 * KSTR + dn * 8) * 2);
                mma16816(o[dn], aP[kp * 2], v00, v01);
                mma16816(o[dn], aP[kp * 2 + 1], v10, v11);
            }
        }
        __syncthreads();   // buf[cur] fully consumed before kt+2 overwrites it
    }

    float inv0 = 1.f / l0, inv1 = 1.f / l1;
    int row0 = s0 + w * 16 + g, row1 = row0 + 8;
#pragma unroll
    for (int dn = 0; dn < 8; dn++) {
        int col = h * DD + dn * 8 + qr * 2;
        float2 v0 = make_float2(o[dn][0] * inv0, o[dn][1] * inv0);
        float2 v1 = make_float2(o[dn][2] * inv1, o[dn][3] * inv1);
        *(float2*)&out[(size_t)(b * SS + row0) * DE + col] = v0;
        *(float2*)&out[(size_t)(b * SS + row1) * DE + col] = v1;
    }
}

extern "C" void kernel_launch(void* const* d_in, const int* in_sizes, int n_in,
                              void* d_out, int out_size) {
    const float* k  = (const float*)d_in[0];
    const float* q  = (const float*)d_in[1];
    const float* v  = (const float*)d_in[2];
    const float* Wk = (const float*)d_in[3];
    const float* Wq = (const float*)d_in[4];
    const float* Wv = (const float*)d_in[5];
    float* out = (float*)d_out;

    dim3 pgrid(SS / 64, HH, 3 * BB);
    proj_kernel<<<pgrid, 128>>>(q, k, v, Wq, Wk, Wv);

    dim3 agrid(SS / 64, HH, BB);
    attn_kernel<<<agrid, 128>>>(out);
}

// round 7
// speedup vs baseline: 1.3197x; 1.3197x over previous
#include <cuda_runtime.h>
#include <cuda_fp16.h>
#include <cstdint>
#include <cstddef>

#define BB 2
#define SS 2048
#define HH 16
#define DD 64
#define DE 1024
#define NT (SS / 64)

// Projected Q/K/V in fp16, layout [b*H + h][s][d]. Q pre-scaled by log2e/8.
__device__ __half g_Q[BB*HH*SS*DD];
__device__ __half g_K[BB*HH*SS*DD];
__device__ __half g_V[BB*HH*SS*DD];

#define KSTR 72                      // smem row stride in halves
#define TILE_BYTES (64 * KSTR * 2)   // 9216 B per K or V buffer

__device__ __forceinline__ void mma16816(float* d, const uint32_t* a,
                                         uint32_t b0, uint32_t b1) {
    asm volatile(
        "mma.sync.aligned.m16n8k16.row.col.f32.f16.f16.f32 "
        "{%0,%1,%2,%3}, {%4,%5,%6,%7}, {%8,%9}, {%0,%1,%2,%3};\n"
        : "+f"(d[0]), "+f"(d[1]), "+f"(d[2]), "+f"(d[3])
        : "r"(a[0]), "r"(a[1]), "r"(a[2]), "r"(a[3]), "r"(b0), "r"(b1));
}

__device__ __forceinline__ void ldsm_x4(uint32_t& r0, uint32_t& r1,
                                        uint32_t& r2, uint32_t& r3, uint32_t a) {
    asm volatile("ldmatrix.sync.aligned.m8n8.x4.shared.b16 {%0,%1,%2,%3}, [%4];\n"
                 : "=r"(r0), "=r"(r1), "=r"(r2), "=r"(r3) : "r"(a));
}

__device__ __forceinline__ void ldsm_x4_t(uint32_t& r0, uint32_t& r1,
                                          uint32_t& r2, uint32_t& r3, uint32_t a) {
    asm volatile("ldmatrix.sync.aligned.m8n8.x4.trans.shared.b16 {%0,%1,%2,%3}, [%4];\n"
                 : "=r"(r0), "=r"(r1), "=r"(r2), "=r"(r3) : "r"(a));
}

__device__ __forceinline__ uint32_t smem_u32(const void* p) {
    return (uint32_t)__cvta_generic_to_shared(p);
}

__device__ __forceinline__ void cp16(uint32_t dst, const void* src) {
    asm volatile("cp.async.ca.shared.global [%0], [%1], 16;\n"
                 :: "r"(dst), "l"(src));
}

__device__ __forceinline__ uint32_t pack2(__half x, __half y) {
    __half2 t = __halves2half2(x, y);
    return *reinterpret_cast<uint32_t*>(&t);
}

// ---------------------------------------------------------------------------
// Projection via hi/lo-split fp16 HMMA (effectively fp32-accurate).
// grid (S/64, H, 3*B), 128 threads = 4 warps; warp w computes 16 s-rows.
// ---------------------------------------------------------------------------
__global__ __launch_bounds__(128) void proj_kernel(const float* __restrict__ xq,
                                                   const float* __restrict__ xk,
                                                   const float* __restrict__ xv,
                                                   const float* __restrict__ Wq,
                                                   const float* __restrict__ Wk,
                                                   const float* __restrict__ Wv) {
    __shared__ __align__(16) __half Xh[64 * KSTR];
    __shared__ __align__(16) __half Xl[64 * KSTR];
    __shared__ __align__(16) __half Wh[64 * KSTR];
    __shared__ __align__(16) __half Wl[64 * KSTR];

    int which = blockIdx.z / BB;          // 0=Q 1=K 2=V
    int b = blockIdx.z % BB;
    int h = blockIdx.y, s0 = blockIdx.x * 64;
    int t = threadIdx.x, w = t >> 5, lane = t & 31;
    int g = lane >> 2, qr = lane & 3;

    const float* x = (which == 0) ? xq : (which == 1) ? xk : xv;
    const float* W = (which == 0) ? Wq : (which == 1) ? Wk : Wv;
    __half* y      = (which == 0) ? g_Q : (which == 1) ? g_K : g_V;
    // Q gets 1/sqrt(64) * log2(e) folded in (softmax runs in exp2 domain)
    float sc = (which == 0) ? 0.125f * 1.44269504088896f : 1.0f;

    const float* xb = x + ((size_t)(b * SS + s0)) * DE + h * DD;
    for (int i = t; i < 4096; i += 128) {
        int r = i >> 6, d = i & 63;
        float xv_ = xb[(size_t)r * DE + d];
        __half hi = __float2half_rn(xv_);
        Xh[r * KSTR + d] = hi;
        Xl[r * KSTR + d] = __float2half_rn(xv_ - __half2float(hi));
        float wv_ = W[i];
        __half whi = __float2half_rn(wv_);
        Wh[r * KSTR + d] = whi;
        Wl[r * KSTR + d] = __float2half_rn(wv_ - __half2float(whi));
    }
    __syncthreads();

    uint32_t aH[4][4], aL[4][4];
    const __half* Xh0 = Xh + (w * 16) * KSTR;
    const __half* Xl0 = Xl + (w * 16) * KSTR;
#pragma unroll
    for (int kk = 0; kk < 4; kk++) {
        int c = kk * 16 + qr * 2;
        aH[kk][0] = *(const uint32_t*)(Xh0 + g * KSTR + c);
        aH[kk][1] = *(const uint32_t*)(Xh0 + (g + 8) * KSTR + c);
        aH[kk][2] = *(const uint32_t*)(Xh0 + g * KSTR + c + 8);
        aH[kk][3] = *(const uint32_t*)(Xh0 + (g + 8) * KSTR + c + 8);
        aL[kk][0] = *(const uint32_t*)(Xl0 + g * KSTR + c);
        aL[kk][1] = *(const uint32_t*)(Xl0 + (g + 8) * KSTR + c);
        aL[kk][2] = *(const uint32_t*)(Xl0 + g * KSTR + c + 8);
        aL[kk][3] = *(const uint32_t*)(Xl0 + (g + 8) * KSTR + c + 8);
    }

    float acc[8][4];
#pragma unroll
    for (int n = 0; n < 8; n++)
#pragma unroll
        for (int j = 0; j < 4; j++) acc[n][j] = 0.f;

    uint32_t whAddr = smem_u32(Wh) + ((lane & 7) * KSTR + (lane >> 3) * 8) * 2;
    uint32_t wlAddr = smem_u32(Wl) + ((lane & 7) * KSTR + (lane >> 3) * 8) * 2;
#pragma unroll
    for (int n = 0; n < 8; n++) {
#pragma unroll
        for (int kp = 0; kp < 2; kp++) {
            uint32_t off = (n * 8 * KSTR + kp * 32) * 2;
            uint32_t h00, h01, h10, h11, l00, l01, l10, l11;
            ldsm_x4(h00, h01, h10, h11, whAddr + off);
            ldsm_x4(l00, l01, l10, l11, wlAddr + off);
            mma16816(acc[n], aH[kp * 2], h00, h01);
            mma16816(acc[n], aL[kp * 2], h00, h01);
            mma16816(acc[n], aH[kp * 2], l00, l01);
            mma16816(acc[n], aH[kp * 2 + 1], h10, h11);
            mma16816(acc[n], aL[kp * 2 + 1], h10, h11);
            mma16816(acc[n], aH[kp * 2 + 1], l10, l11);
        }
    }

    __half* yb = y + ((size_t)(b * HH + h) * SS + s0) * DD;
    int r0 = w * 16 + g, r1 = r0 + 8;
#pragma unroll
    for (int n = 0; n < 8; n++) {
        int col = n * 8 + qr * 2;
        *(uint32_t*)(yb + (size_t)r0 * DD + col) =
            pack2(__float2half_rn(acc[n][0] * sc), __float2half_rn(acc[n][1] * sc));
        *(uint32_t*)(yb + (size_t)r1 * DD + col) =
            pack2(__float2half_rn(acc[n][2] * sc), __float2half_rn(acc[n][3] * sc));
    }
}

// ---------------------------------------------------------------------------
// Tensor-core flash attention. CTA = 128 q-rows (4 warps x 32 rows = 2 A-tiles
// per warp) so each ldmatrix'd K/V fragment feeds 4 MMAs -> half the smem
// traffic of the 64-row version. cp.async double-buffered K/V, exp2 softmax.
// grid (S/128, H, B), 128 threads, 2 CTAs/SM.
// ---------------------------------------------------------------------------
__global__ __launch_bounds__(128, 2) void attn_kernel(float* __restrict__ out) {
    __shared__ __align__(16) __half Ks[2][64 * KSTR];
    __shared__ __align__(16) __half Vs[2][64 * KSTR];

    int b = blockIdx.z, h = blockIdx.y, s0 = blockIdx.x * 128;
    int t = threadIdx.x, w = t >> 5, lane = t & 31;
    int g = lane >> 2, qr = lane & 3;
    size_t bh = (size_t)(b * HH + h);
    const __half* Qg = g_Q + bh * SS * DD + (size_t)(s0 + w * 32) * DD;
    const __half* Kg = g_K + bh * SS * DD;
    const __half* Vg = g_V + bh * SS * DD;

    // per-thread cp.async targets: 4 contiguous 16B chunks (=64B) per tensor
    int c0 = t * 4;                                  // chunk index, 8 chunks/row
    uint32_t ksDst = smem_u32(&Ks[0][(c0 >> 3) * KSTR + (c0 & 7) * 8]);
    uint32_t vsDst = smem_u32(&Vs[0][(c0 >> 3) * KSTR + (c0 & 7) * 8]);

    // Q A-fragments for both 16-row m-tiles, persistent.
    uint32_t aQ[2][4][4];
#pragma unroll
    for (int mt = 0; mt < 2; mt++) {
        const __half* Qm = Qg + (size_t)(mt * 16) * DD;
#pragma unroll
        for (int kk = 0; kk < 4; kk++) {
            int c = kk * 16 + qr * 2;
            aQ[mt][kk][0] = *(const uint32_t*)(Qm + (size_t)g * DD + c);
            aQ[mt][kk][1] = *(const uint32_t*)(Qm + (size_t)(g + 8) * DD + c);
            aQ[mt][kk][2] = *(const uint32_t*)(Qm + (size_t)g * DD + c + 8);
            aQ[mt][kk][3] = *(const uint32_t*)(Qm + (size_t)(g + 8) * DD + c + 8);
        }
    }

    float o[2][8][4];
#pragma unroll
    for (int mt = 0; mt < 2; mt++)
#pragma unroll
        for (int dn = 0; dn < 8; dn++)
#pragma unroll
            for (int j = 0; j < 4; j++) o[mt][dn][j] = 0.f;
    float m0[2] = {-1e30f, -1e30f}, m1[2] = {-1e30f, -1e30f};
    float l0[2] = {0.f, 0.f}, l1[2] = {0.f, 0.f};

    uint32_t kAddr = smem_u32(Ks) + ((lane & 7) * KSTR + (lane >> 3) * 8) * 2;
    uint32_t vAddr = smem_u32(Vs) + (lane * KSTR) * 2;

    // prologue: stage tile 0 into buffer 0
#pragma unroll
    for (int j = 0; j < 4; j++) {
        cp16(ksDst + j * 16, Kg + (size_t)(c0 + j) * 8);
        cp16(vsDst + j * 16, Vg + (size_t)(c0 + j) * 8);
    }
    asm volatile("cp.async.commit_group;\n");

    for (int kt = 0; kt < NT; kt++) {
        int cur = kt & 1;
        if (kt + 1 < NT) {
            const __half* K1 = Kg + (size_t)(kt + 1) * 64 * DD;
            const __half* V1 = Vg + (size_t)(kt + 1) * 64 * DD;
            uint32_t kd = ksDst + (cur ^ 1) * TILE_BYTES;
            uint32_t vd = vsDst + (cur ^ 1) * TILE_BYTES;
#pragma unroll
            for (int j = 0; j < 4; j++) {
                cp16(kd + j * 16, K1 + (size_t)(c0 + j) * 8);
                cp16(vd + j * 16, V1 + (size_t)(c0 + j) * 8);
            }
            asm volatile("cp.async.commit_group;\n");
            asm volatile("cp.async.wait_group 1;\n");
        } else {
            asm volatile("cp.async.wait_group 0;\n");
        }
        __syncthreads();

        uint32_t kA = kAddr + cur * TILE_BYTES;
        uint32_t vA = vAddr + cur * TILE_BYTES;

        // S = Q K^T : each K fragment feeds both m-tiles
        float s[2][8][4];
#pragma unroll
        for (int n = 0; n < 8; n++) {
#pragma unroll
            for (int j = 0; j < 4; j++) { s[0][n][j] = 0.f; s[1][n][j] = 0.f; }
#pragma unroll
            for (int kp = 0; kp < 2; kp++) {
                uint32_t b00, b01, b10, b11;
                ldsm_x4(b00, b01, b10, b11, kA + (n * 8 * KSTR + kp * 32) * 2);
                mma16816(s[0][n], aQ[0][kp * 2], b00, b01);
                mma16816(s[0][n], aQ[0][kp * 2 + 1], b10, b11);
                mma16816(s[1][n], aQ[1][kp * 2], b00, b01);
                mma16816(s[1][n], aQ[1][kp * 2 + 1], b10, b11);
            }
        }

        // streaming softmax in exp2 domain, per m-tile
        uint32_t aP[2][4][4];
#pragma unroll
        for (int mt = 0; mt < 2; mt++) {
            float rx0 = -1e30f, rx1 = -1e30f;
#pragma unroll
            for (int n = 0; n < 8; n++) {
                rx0 = fmaxf(rx0, fmaxf(s[mt][n][0], s[mt][n][1]));
                rx1 = fmaxf(rx1, fmaxf(s[mt][n][2], s[mt][n][3]));
            }
            rx0 = fmaxf(rx0, __shfl_xor_sync(0xffffffffu, rx0, 1));
            rx0 = fmaxf(rx0, __shfl_xor_sync(0xffffffffu, rx0, 2));
            rx1 = fmaxf(rx1, __shfl_xor_sync(0xffffffffu, rx1, 1));
            rx1 = fmaxf(rx1, __shfl_xor_sync(0xffffffffu, rx1, 2));
            float mn0 = fmaxf(m0[mt], rx0), mn1 = fmaxf(m1[mt], rx1);
            float cf0 = exp2f(m0[mt] - mn0), cf1 = exp2f(m1[mt] - mn1);
            m0[mt] = mn0; m1[mt] = mn1;

            float sum0 = 0.f, sum1 = 0.f;
#pragma unroll
            for (int n = 0; n < 8; n++) {
                float e0 = exp2f(s[mt][n][0] - mn0);
                float e1 = exp2f(s[mt][n][1] - mn0);
                float e2 = exp2f(s[mt][n][2] - mn1);
                float e3 = exp2f(s[mt][n][3] - mn1);
                sum0 += e0 + e1; sum1 += e2 + e3;
                aP[mt][n >> 1][(n & 1) * 2 + 0] =
                    pack2(__float2half_rn(e0), __float2half_rn(e1));
                aP[mt][n >> 1][(n & 1) * 2 + 1] =
                    pack2(__float2half_rn(e2), __float2half_rn(e3));
            }
            sum0 += __shfl_xor_sync(0xffffffffu, sum0, 1);
            sum0 += __shfl_xor_sync(0xffffffffu, sum0, 2);
            sum1 += __shfl_xor_sync(0xffffffffu, sum1, 1);
            sum1 += __shfl_xor_sync(0xffffffffu, sum1, 2);
            l0[mt] = l0[mt] * cf0 + sum0;
            l1[mt] = l1[mt] * cf1 + sum1;

#pragma unroll
            for (int dn = 0; dn < 8; dn++) {
                o[mt][dn][0] *= cf0; o[mt][dn][1] *= cf0;
                o[mt][dn][2] *= cf1; o[mt][dn][3] *= cf1;
            }
        }

        // O += P @ V : each V fragment feeds both m-tiles
#pragma unroll
        for (int dn = 0; dn < 8; dn++) {
#pragma unroll
            for (int kp = 0; kp < 2; kp++) {
                uint32_t v00, v01, v10, v11;
                ldsm_x4_t(v00, v01, v10, v11,
                          vA + (kp * 32 * KSTR + dn * 8) * 2);
                mma16816(o[0][dn], aP[0][kp * 2], v00, v01);
                mma16816(o[0][dn], aP[0][kp * 2 + 1], v10, v11);
                mma16816(o[1][dn], aP[1][kp * 2], v00, v01);
                mma16816(o[1][dn], aP[1][kp * 2 + 1], v10, v11);
            }
        }
        __syncthreads();   // buf[cur] fully consumed before kt+2 overwrites it
    }

#pragma unroll
    for (int mt = 0; mt < 2; mt++) {
        float inv0 = 1.f / l0[mt], inv1 = 1.f / l1[mt];
        int row0 = s0 + w * 32 + mt * 16 + g, row1 = row0 + 8;
#pragma unroll
        for (int dn = 0; dn < 8; dn++) {
            int col = h * DD + dn * 8 + qr * 2;
            float2 v0 = make_float2(o[mt][dn][0] * inv0, o[mt][dn][1] * inv0);
            float2 v1 = make_float2(o[mt][dn][2] * inv1, o[mt][dn][3] * inv1);
            *(float2*)&out[(size_t)(b * SS + row0) * DE + col] = v0;
            *(float2*)&out[(size_t)(b * SS + row1) * DE + col] = v1;
        }
    }
}

extern "C" void kernel_launch(void* const* d_in, const int* in_sizes, int n_in,
                              void* d_out, int out_size) {
    const float* k  = (const float*)d_in[0];
    const float* q  = (const float*)d_in[1];
    const float* v  = (const float*)d_in[2];
    const float* Wk = (const float*)d_in[3];
    const float* Wq = (const float*)d_in[4];
    const float* Wv = (const float*)d_in[5];
    float* out = (float*)d_out;

    dim3 pgrid(SS / 64, HH, 3 * BB);
    proj_kernel<<<pgrid, 128>>>(q, k, v, Wq, Wk, Wv);

    dim3 agrid(SS / 128, HH, BB);
    attn_kernel<<<agrid, 128>>>(out);
}